// round 10
// baseline (speedup 1.0000x reference)
#include <cuda_runtime.h>
#include <cstdint>

#define NT   9
#define NPIX 65536
#define NB   16

typedef unsigned long long ull;

// ---------------------------------------------------------------------------
// Packed f32x2 helpers (Blackwell fma.rn.f32x2, PTX-only)
// ---------------------------------------------------------------------------
__device__ __forceinline__ ull pack2(float a, float b) {
    ull r;
    asm("mov.b64 %0, {%1,%2};" : "=l"(r) : "f"(a), "f"(b));
    return r;
}
__device__ __forceinline__ void unpack2(ull v, float& a, float& b) {
    asm("mov.b64 {%0,%1}, %2;" : "=f"(a), "=f"(b) : "l"(v));
}
__device__ __forceinline__ void fma2(ull& acc, ull v, ull w) {
    asm("fma.rn.f32x2 %0, %1, %2, %3;" : "=l"(acc) : "l"(v), "l"(w), "l"(acc));
}

__device__ __forceinline__ float sp10(float x) {
    float z = 10.0f * x;
    return fmaxf(x, 0.0f) + 0.1f * log1pf(expf(-fabsf(z)));
}

// ---------------------------------------------------------------------------
// Scratch (device globals — allocation-free)
// ---------------------------------------------------------------------------
__device__ float g_p1[(size_t)NB * 10 * NPIX];
__device__ float g_p2[(size_t)NB * 20 * NPIX];
__device__ float g_KG [(size_t)NB * NT * NPIX];
__device__ float g_M1 [(size_t)NB * NT * NPIX];
__device__ float g_M2 [(size_t)NB * NT * NPIX];
__device__ float g_H11[(size_t)NB * NT * NPIX];
__device__ float g_HB [(size_t)NB * NT * NPIX];
__device__ float g_H22[(size_t)NB * NT * NPIX];
__device__ float g_part[NB * 64];

// ---------------------------------------------------------------------------
// Direct 3x3 SAME conv (conv1 / conv2), NCHW/OIHW, zero pad.
// Weights staged in smem with COUT padded to COUT_P (16B-aligned tap stride)
// so pairs of f32x2 weights load as a single LDS.128 (halves LSU pressure).
// ---------------------------------------------------------------------------
template <int CIN, int COUT, int COUT_P, int CCH, int ROWS, bool RELU>
__device__ __forceinline__ void conv_body(const float* __restrict__ in,
                                          const float* __restrict__ wt,
                                          float* __restrict__ out,
                                          int b) {
    constexpr int TH = 4 * ROWS;
    constexpr int HR = TH + 2;
    __shared__ __align__(16) float s_w[CIN * 9 * COUT_P];
    __shared__ float s_in[CCH][HR][34];

    const int x0 = blockIdx.x * 32;
    const int y0 = blockIdx.y * TH;
    const int tx = threadIdx.x;
    const int ty = threadIdx.y;
    const int tid = ty * 32 + tx;

    for (int i = tid; i < CIN * 9 * COUT; i += 128) {
        int co = i % COUT;
        int r  = i / COUT;
        int ci = r / 9, tap = r % 9;
        s_w[(ci * 9 + tap) * COUT_P + co] = wt[(co * CIN + ci) * 9 + tap];
    }

    ull acc[ROWS][COUT / 2];
#pragma unroll
    for (int k = 0; k < ROWS; k++)
#pragma unroll
        for (int j = 0; j < COUT / 2; j++) acc[k][j] = 0ull;

    const float* inb = in + (size_t)b * CIN * NPIX;

    for (int cch0 = 0; cch0 < CIN; cch0 += CCH) {
        __syncthreads();
        for (int i = tid; i < CCH * HR * 34; i += 128) {
            int ci = i / (HR * 34);
            int rr = (i / 34) % HR;
            int cc = i % 34;
            int gy = y0 + rr - 1, gx = x0 + cc - 1;
            float v = 0.0f;
            if ((unsigned)gy < 256u && (unsigned)gx < 256u) {
                v = inb[(size_t)(cch0 + ci) * NPIX + gy * 256 + gx];
                if (RELU) v = fmaxf(v, 0.0f);
            }
            s_in[ci][rr][cc] = v;
        }
        __syncthreads();

#pragma unroll 1
        for (int cl = 0; cl < CCH; ++cl) {
            ull pv[ROWS + 2][3];
#pragma unroll
            for (int rr = 0; rr < ROWS + 2; rr++)
#pragma unroll
                for (int c = 0; c < 3; c++) {
                    float vv = s_in[cl][ty * ROWS + rr][tx + c];
                    pv[rr][c] = pack2(vv, vv);
                }

            const float* wp = s_w + (size_t)(cch0 + cl) * 9 * COUT_P;
#pragma unroll
            for (int ky = 0; ky < 3; ky++)
#pragma unroll
                for (int kx = 0; kx < 3; kx++) {
                    const float* wt0 = wp + (ky * 3 + kx) * COUT_P;
#pragma unroll
                    for (int j2 = 0; j2 < COUT / 4; j2++) {
                        ulonglong2 ww = ((const ulonglong2*)wt0)[j2];
#pragma unroll
                        for (int r = 0; r < ROWS; r++) {
                            fma2(acc[r][2 * j2],     pv[ky + r][kx], ww.x);
                            fma2(acc[r][2 * j2 + 1], pv[ky + r][kx], ww.y);
                        }
                    }
                    if (COUT % 4) {          // one leftover pair
                        ull w = ((const ull*)wt0)[COUT / 2 - 1];
#pragma unroll
                        for (int r = 0; r < ROWS; r++)
                            fma2(acc[r][COUT / 2 - 1], pv[ky + r][kx], w);
                    }
                }
        }
    }

    float* outb = out + (size_t)b * COUT * NPIX;
#pragma unroll
    for (int r = 0; r < ROWS; r++) {
        const int y = y0 + ty * ROWS + r;
#pragma unroll
        for (int j = 0; j < COUT / 2; j++) {
            float a, bb;
            unpack2(acc[r][j], a, bb);
            outb[(size_t)(2 * j)     * NPIX + y * 256 + x0 + tx] = a;
            outb[(size_t)(2 * j + 1) * NPIX + y * 256 + x0 + tx] = bb;
        }
    }
}

__global__ void __launch_bounds__(128) k_conv1(const float* __restrict__ x,
                                               const float* __restrict__ w,
                                               int b_off) {
    conv_body<9, 10, 12, 9, 4, true>(x, w, g_p1, blockIdx.z + b_off);
}
__global__ void __launch_bounds__(128) k_conv2(const float* __restrict__ w) {
    conv_body<10, 20, 20, 10, 4, true>(g_p1, w, g_p2, blockIdx.z);
}

// ---------------------------------------------------------------------------
// conv3 FUSED (validated R8 epilogue):
//  - kappa/m flat outputs: elementwise in PLANE layout, direct stores.
//  - H flat output: per-pixel n*9+t layout, smem-staged float4 stores.
//  - H grids: PLANE layout, direct stores.
//  - KG/M1/M2 grids built later by k_gridkgm from out_kap/out_m.
// ---------------------------------------------------------------------------
__global__ void __launch_bounds__(128) k_conv3f(const float* __restrict__ wt,
                                                float* __restrict__ out_kap,
                                                float* __restrict__ out_m,
                                                float* __restrict__ out_H) {
    constexpr int CIN = 20, COUT = 54, COUT_P = 56, CCH = 5, ROWS = 2;
    constexpr int TH = 8, HR = 10;
    __shared__ __align__(16) float s_w[CIN * 9 * COUT_P];   // 40320 B
    __shared__ float s_in[CCH][HR][34];

    const int b  = blockIdx.z;
    const int x0 = blockIdx.x * 32;
    const int y0 = blockIdx.y * TH;
    const int tx = threadIdx.x;
    const int ty = threadIdx.y;
    const int tid = ty * 32 + tx;

    for (int i = tid; i < CIN * 9 * COUT; i += 128) {
        int co = i % COUT;
        int r  = i / COUT;
        int ci = r / 9, tap = r % 9;
        s_w[(ci * 9 + tap) * COUT_P + co] = wt[(co * CIN + ci) * 9 + tap];
    }

    ull acc[ROWS][COUT / 2];
#pragma unroll
    for (int k = 0; k < ROWS; k++)
#pragma unroll
        for (int j = 0; j < COUT / 2; j++) acc[k][j] = 0ull;

    const float* inb = g_p2 + (size_t)b * CIN * NPIX;

    for (int cch0 = 0; cch0 < CIN; cch0 += CCH) {
        __syncthreads();
        for (int i = tid; i < CCH * HR * 34; i += 128) {
            int ci = i / (HR * 34);
            int rr = (i / 34) % HR;
            int cc = i % 34;
            int gy = y0 + rr - 1, gx = x0 + cc - 1;
            float v = 0.0f;
            if ((unsigned)gy < 256u && (unsigned)gx < 256u)
                v = inb[(size_t)(cch0 + ci) * NPIX + gy * 256 + gx];
            s_in[ci][rr][cc] = v;
        }
        __syncthreads();

#pragma unroll 1
        for (int cl = 0; cl < CCH; ++cl) {
            ull pv[ROWS + 2][3];
#pragma unroll
            for (int rr = 0; rr < ROWS + 2; rr++)
#pragma unroll
                for (int c = 0; c < 3; c++) {
                    float vv = s_in[cl][ty * ROWS + rr][tx + c];
                    pv[rr][c] = pack2(vv, vv);
                }

            const float* wp = s_w + (size_t)(cch0 + cl) * 9 * COUT_P;
#pragma unroll
            for (int ky = 0; ky < 3; ky++)
#pragma unroll
                for (int kx = 0; kx < 3; kx++) {
                    const float* wt0 = wp + (ky * 3 + kx) * COUT_P;
#pragma unroll
                    for (int j2 = 0; j2 < COUT / 4; j2++) {   // 13 x LDS.128
                        ulonglong2 ww = ((const ulonglong2*)wt0)[j2];
#pragma unroll
                        for (int r = 0; r < ROWS; r++) {
                            fma2(acc[r][2 * j2],     pv[ky + r][kx], ww.x);
                            fma2(acc[r][2 * j2 + 1], pv[ky + r][kx], ww.y);
                        }
                    }
                    {   // leftover pair 26 (co 52,53)
                        ull w = ((const ull*)wt0)[26];
#pragma unroll
                        for (int r = 0; r < ROWS; r++)
                            fma2(acc[r][26], pv[ky + r][kx], w);
                    }
                }
        }
    }

    // ---- epilogue ------------------------------------------------------
    __syncthreads();                 // all warps done with s_w / s_in
    float* sf = s_w;                 // H staging: 3 * 2304 floats

    const size_t pb   = (size_t)b * NT * NPIX;
    const size_t pix0 = (size_t)(y0 + ty * ROWS) * 256 + (x0 + tx);
    float* okb = out_kap + (size_t)b * 9 * NPIX;
    float* omb = out_m   + (size_t)b * 18 * NPIX;

    float vh[ROWS][27];              // channels 27..53 per row

#pragma unroll
    for (int r = 0; r < ROWS; r++) {
        const size_t pix = pix0 + (size_t)r * 256;
#pragma unroll
        for (int j = 0; j < 13; j++) {
            float lo, hi;
            unpack2(acc[r][j], lo, hi);
            const int c0 = 2 * j, c1 = 2 * j + 1;
            if (c0 < 9) okb[(size_t)c0 * NPIX + pix] = sp10(lo);
            else        omb[(size_t)(c0 - 9) * NPIX + pix] = lo;
            if (c1 < 9) okb[(size_t)c1 * NPIX + pix] = sp10(hi);
            else        omb[(size_t)(c1 - 9) * NPIX + pix] = hi;
        }
        {
            float lo, hi;
            unpack2(acc[r][13], lo, hi);
            omb[(size_t)17 * NPIX + pix] = lo;
            vh[r][0] = hi;
        }
#pragma unroll
        for (int j = 14; j < 27; j++) {
            float lo, hi;
            unpack2(acc[r][j], lo, hi);
            vh[r][2 * j - 27] = lo;
            vh[r][2 * j - 26] = hi;
        }
    }

    // H: planes (coalesced) + stage flat (n*9+t layout)
#pragma unroll
    for (int r = 0; r < ROWS; r++) {
        const size_t pix = pix0 + (size_t)r * 256;
        float* st = sf + (size_t)(ty * ROWS + r) * 288 + tx * 9;
#pragma unroll
        for (int t = 0; t < 9; t++) {
            float gsp = sp10(vh[r][t]);
            float vx  = vh[r][9 + t];
            float vy  = vh[r][18 + t];
            float h00 = gsp + vx * vx;
            float cd  = vx * vy;
            float h11 = gsp + vy * vy;
            g_H11[pb + (size_t)t * NPIX + pix] = h00;
            g_HB [pb + (size_t)t * NPIX + pix] = 2.0f * cd;
            g_H22[pb + (size_t)t * NPIX + pix] = h11;
            st[t]            = h00;
            st[2304 + t]     = cd;
            st[2 * 2304 + t] = h11;
        }
    }
    __syncthreads();
    {
        float4* d00 = (float4*)(out_H + (size_t)(b * 4 + 0) * 9 * NPIX);
        float4* d01 = (float4*)(out_H + (size_t)(b * 4 + 1) * 9 * NPIX);
        float4* d10 = (float4*)(out_H + (size_t)(b * 4 + 2) * 9 * NPIX);
        float4* d11 = (float4*)(out_H + (size_t)(b * 4 + 3) * 9 * NPIX);
        const int xo4 = x0 * 9 / 4;
        for (int i = tid; i < 576; i += 128) {
            int row = i / 72, jj = i - row * 72;
            size_t o4 = (size_t)(y0 + row) * 576 + xo4 + jj;
            int s4 = row * 72 + jj;
            float4 cd4 = ((float4*)(sf + 2304))[s4];
            d00[o4] = ((float4*)sf)[s4];
            d01[o4] = cd4;
            d10[o4] = cd4;
            d11[o4] = ((float4*)(sf + 2 * 2304))[s4];
        }
    }
}

// ---------------------------------------------------------------------------
// KG/M1/M2 grids from the flat outputs (scrambled reinterpretation):
//   g_KG[b,t,n] = out_kap_flat[b, n*9+t]
// ---------------------------------------------------------------------------
__global__ void __launch_bounds__(256) k_gridkgm(const float* __restrict__ ok,
                                                 const float* __restrict__ om) {
    __shared__ float sk[2304], s1[2304], s2[2304];
    const int blk = blockIdx.x;
    const int b  = blk >> 8;
    const int n0 = (blk & 255) * 256;
    const int tid = threadIdx.x;

    const float4* pk  = (const float4*)(ok + (size_t)b * 9 * NPIX + (size_t)n0 * 9);
    const float4* pm1 = (const float4*)(om + (size_t)b * 18 * NPIX + (size_t)n0 * 9);
    const float4* pm2 = (const float4*)(om + (size_t)b * 18 * NPIX + (size_t)9 * NPIX + (size_t)n0 * 9);
    for (int i = tid; i < 576; i += 256) {
        ((float4*)sk)[i] = pk[i];
        ((float4*)s1)[i] = pm1[i];
        ((float4*)s2)[i] = pm2[i];
    }
    __syncthreads();

    const int n = n0 + tid;
    const size_t gb = (size_t)b * NT * NPIX + n;
#pragma unroll
    for (int t = 0; t < 9; t++) {
        g_KG[gb + (size_t)t * NPIX] = sk[tid * 9 + t];
        g_M1[gb + (size_t)t * NPIX] = s1[tid * 9 + t];
        g_M2[gb + (size_t)t * NPIX] = s2[tid * 9 + t];
    }
}

// ---------------------------------------------------------------------------
// Fused stencil (unchanged): w = M(xg) on 34x34 halo, v = M(w) on 32x32,
// accumulate x_out terms with rotating registers.
// ---------------------------------------------------------------------------
__device__ __forceinline__ float stencil_A(float u, float xpv, float xmv,
                                           float ypv, float ymv,
                                           float pp, float pm, float mp, float mm,
                                           float kap, float m1, float m2,
                                           float h11, float hb, float h22) {
    return kap * kap * u
         + m1 * 0.5f * (xpv - xmv)
         + m2 * 0.5f * (ypv - ymv)
         - (h11 * (xpv - 2.0f * u + xmv)
            + hb * 0.25f * ((pp - pm) - (mp - mm))
            + h22 * (ypv - 2.0f * u + ymv));
}

__global__ void __launch_bounds__(256) k_stencil(const float* __restrict__ x) {
    __shared__ float s_xg[36][37];
    __shared__ float s_co[6][34][35];
    __shared__ float s_w[34][36];
    __shared__ float s_red[8];

    const int b  = blockIdx.z;
    const int a0 = blockIdx.y * 32;
    const int c0 = blockIdx.x * 32;
    const int tid = threadIdx.x;

    float xgp[4], wprev[4];
#pragma unroll
    for (int j = 0; j < 4; j++) { xgp[j] = 0.0f; wprev[j] = 0.0f; }
    float acc = 0.0f;

    for (int t = 0; t < 9; t++) {
        __syncthreads();
        const float* xp = x + (size_t)(b * 9 + t) * NPIX;
        for (int i = tid; i < 1296; i += 256) {
            int xr = i / 36, xc = i - xr * 36;
            int gc = c0 - 2 + xr, ga = a0 - 2 + xc;
            float v = 0.0f;
            if ((unsigned)gc < 256u && (unsigned)ga < 256u)
                v = xp[gc * 256 + ga];
            s_xg[xc][xr] = v;
        }
        const size_t pbase = (size_t)(b * 9 + t) * NPIX;
        for (int i = tid; i < 1156; i += 256) {
            int r = i / 34, c = i - r * 34;
            int ga = a0 - 1 + r, gc = c0 - 1 + c;
            bool ok = ((unsigned)ga < 256u) && ((unsigned)gc < 256u);
            size_t idx = pbase + (size_t)ga * 256 + gc;
            s_co[0][r][c] = ok ? g_KG [idx] : 0.0f;
            s_co[1][r][c] = ok ? g_M1 [idx] : 0.0f;
            s_co[2][r][c] = ok ? g_M2 [idx] : 0.0f;
            s_co[3][r][c] = ok ? g_H11[idx] : 0.0f;
            s_co[4][r][c] = ok ? g_HB [idx] : 0.0f;
            s_co[5][r][c] = ok ? g_H22[idx] : 0.0f;
        }
        __syncthreads();

        for (int i = tid; i < 1156; i += 256) {
            int r = i / 34, c = i - r * 34;
            int ga = a0 - 1 + r, gc = c0 - 1 + c;
            float w = 0.0f;
            if ((unsigned)ga < 256u && (unsigned)gc < 256u) {
                float u   = s_xg[r + 1][c + 1];
                float xpv = s_xg[r + 2][c + 1], xmv = s_xg[r][c + 1];
                float ypv = s_xg[r + 1][c + 2], ymv = s_xg[r + 1][c];
                float pp  = s_xg[r + 2][c + 2], pm  = s_xg[r + 2][c];
                float mp  = s_xg[r][c + 2],     mm  = s_xg[r][c];
                w = u + stencil_A(u, xpv, xmv, ypv, ymv, pp, pm, mp, mm,
                                  s_co[0][r][c], s_co[1][r][c], s_co[2][r][c],
                                  s_co[3][r][c], s_co[4][r][c], s_co[5][r][c]);
            }
            s_w[r][c] = w;
        }
        __syncthreads();

#pragma unroll
        for (int j = 0; j < 4; j++) {
            int p = tid + j * 256;
            int r = p >> 5, c = p & 31;
            float u   = s_w[r + 1][c + 1];
            float xpv = s_w[r + 2][c + 1], xmv = s_w[r][c + 1];
            float ypv = s_w[r + 1][c + 2], ymv = s_w[r + 1][c];
            float pp  = s_w[r + 2][c + 2], pm  = s_w[r + 2][c];
            float mp  = s_w[r][c + 2],     mm  = s_w[r][c];
            float v = u + stencil_A(u, xpv, xmv, ypv, ymv, pp, pm, mp, mm,
                                    s_co[0][r + 1][c + 1], s_co[1][r + 1][c + 1],
                                    s_co[2][r + 1][c + 1], s_co[3][r + 1][c + 1],
                                    s_co[4][r + 1][c + 1], s_co[5][r + 1][c + 1]);
            float xgc = s_xg[r + 2][c + 2];
            acc += xgc * v;
            if (t >= 1 && t <= 7) acc += xgc * xgc;
            if (t >= 1) acc -= u * xgp[j] + wprev[j] * xgc;
            xgp[j]   = xgc;
            wprev[j] = u;
        }
    }

#pragma unroll
    for (int o = 16; o > 0; o >>= 1)
        acc += __shfl_down_sync(0xffffffffu, acc, o);
    if ((tid & 31) == 0) s_red[tid >> 5] = acc;
    __syncthreads();
    if (tid == 0) {
        float s = 0.0f;
#pragma unroll
        for (int i = 0; i < 8; i++) s += s_red[i];
        g_part[b * 64 + blockIdx.y * 8 + blockIdx.x] = s;
    }
}

__global__ void __launch_bounds__(64) k_final(float* __restrict__ out_x) {
    __shared__ float s[2];
    int b = blockIdx.x, tid = threadIdx.x;
    float v = g_part[b * 64 + tid];
#pragma unroll
    for (int o = 16; o > 0; o >>= 1)
        v += __shfl_down_sync(0xffffffffu, v, o);
    if ((tid & 31) == 0) s[tid >> 5] = v;
    __syncthreads();
    if (tid == 0) out_x[b] = s[0] + s[1];
}

// ---------------------------------------------------------------------------
// Launch. conv1 split in two so conv3f lands at profiled launch slot #4.
// Output: [x_out(16)] [kappa_r 16*9*65536] [m_r 16*18*65536] [H_r 16*4*9*65536]
// ---------------------------------------------------------------------------
extern "C" void kernel_launch(void* const* d_in, const int* in_sizes, int n_in,
                              void* d_out, int out_size) {
    (void)in_sizes; (void)n_in; (void)out_size;
    const float* x  = (const float*)d_in[0];
    const float* w1 = (const float*)d_in[4];
    const float* w2 = (const float*)d_in[5];
    const float* w3 = (const float*)d_in[6];

    float* out     = (float*)d_out;
    float* out_kap = out + 16;
    float* out_m   = out + 16 + (size_t)NB * 9 * NPIX;
    float* out_H   = out + 16 + (size_t)NB * 9 * NPIX + (size_t)NB * 18 * NPIX;

    dim3 cb(32, 4);
    k_conv1 <<<dim3(8, 16, 8),  cb>>>(x, w1, 0);
    k_conv1 <<<dim3(8, 16, 8),  cb>>>(x, w1, 8);
    k_conv2 <<<dim3(8, 16, NB), cb>>>(w2);
    k_conv3f<<<dim3(8, 32, NB), cb>>>(w3, out_kap, out_m, out_H);

    k_gridkgm<<<4096, 256>>>(out_kap, out_m);

    k_stencil<<<dim3(8, 8, NB), 256>>>(x);
    k_final  <<<NB, 64>>>(out);
}

// round 14
// speedup vs baseline: 1.0572x; 1.0572x over previous
#include <cuda_runtime.h>
#include <cstdint>

#define NT   9
#define NPIX 65536
#define NB   16

typedef unsigned long long ull;

// ---------------------------------------------------------------------------
// Packed f32x2 helpers (Blackwell fma.rn.f32x2, PTX-only)
// ---------------------------------------------------------------------------
__device__ __forceinline__ ull pack2(float a, float b) {
    ull r;
    asm("mov.b64 %0, {%1,%2};" : "=l"(r) : "f"(a), "f"(b));
    return r;
}
__device__ __forceinline__ void unpack2(ull v, float& a, float& b) {
    asm("mov.b64 {%0,%1}, %2;" : "=f"(a), "=f"(b) : "l"(v));
}
__device__ __forceinline__ void fma2(ull& acc, ull v, ull w) {
    asm("fma.rn.f32x2 %0, %1, %2, %3;" : "=l"(acc) : "l"(v), "l"(w), "l"(acc));
}

__device__ __forceinline__ float sp10(float x) {
    float z = 10.0f * x;
    return fmaxf(x, 0.0f) + 0.1f * log1pf(expf(-fabsf(z)));
}

// ---------------------------------------------------------------------------
// Scratch (device globals — allocation-free)
// ---------------------------------------------------------------------------
__device__ float g_p1[(size_t)NB * 10 * NPIX];
__device__ float g_p2[(size_t)NB * 20 * NPIX];
__device__ float g_KG [(size_t)NB * NT * NPIX];
__device__ float g_M1 [(size_t)NB * NT * NPIX];
__device__ float g_M2 [(size_t)NB * NT * NPIX];
__device__ float g_H11[(size_t)NB * NT * NPIX];
__device__ float g_HB [(size_t)NB * NT * NPIX];
__device__ float g_H22[(size_t)NB * NT * NPIX];
__device__ float g_part[NB * 64];

// ---------------------------------------------------------------------------
// Direct 3x3 SAME conv (conv1 / conv2) — R8-validated form (LDS.64 weights).
// ---------------------------------------------------------------------------
template <int CIN, int COUT, int CCH, int ROWS, bool RELU>
__device__ __forceinline__ void conv_body(const float* __restrict__ in,
                                          const float* __restrict__ wt,
                                          float* __restrict__ out,
                                          int b) {
    constexpr int TH = 4 * ROWS;
    constexpr int HR = TH + 2;
    __shared__ __align__(16) float s_w[CIN * 9 * COUT];
    __shared__ float s_in[CCH][HR][34];

    const int x0 = blockIdx.x * 32;
    const int y0 = blockIdx.y * TH;
    const int tx = threadIdx.x;
    const int ty = threadIdx.y;
    const int tid = ty * 32 + tx;

    for (int i = tid; i < CIN * 9 * COUT; i += 128) {
        int co = i % COUT;
        int r  = i / COUT;
        int ci = r / 9, tap = r % 9;
        s_w[i] = wt[(co * CIN + ci) * 9 + tap];
    }

    ull acc[ROWS][COUT / 2];
#pragma unroll
    for (int k = 0; k < ROWS; k++)
#pragma unroll
        for (int j = 0; j < COUT / 2; j++) acc[k][j] = 0ull;

    const float* inb = in + (size_t)b * CIN * NPIX;

    for (int cch0 = 0; cch0 < CIN; cch0 += CCH) {
        __syncthreads();
        for (int i = tid; i < CCH * HR * 34; i += 128) {
            int ci = i / (HR * 34);
            int rr = (i / 34) % HR;
            int cc = i % 34;
            int gy = y0 + rr - 1, gx = x0 + cc - 1;
            float v = 0.0f;
            if ((unsigned)gy < 256u && (unsigned)gx < 256u) {
                v = inb[(size_t)(cch0 + ci) * NPIX + gy * 256 + gx];
                if (RELU) v = fmaxf(v, 0.0f);
            }
            s_in[ci][rr][cc] = v;
        }
        __syncthreads();

#pragma unroll 1
        for (int cl = 0; cl < CCH; ++cl) {
            ull pv[ROWS + 2][3];
#pragma unroll
            for (int rr = 0; rr < ROWS + 2; rr++)
#pragma unroll
                for (int c = 0; c < 3; c++) {
                    float vv = s_in[cl][ty * ROWS + rr][tx + c];
                    pv[rr][c] = pack2(vv, vv);
                }

            const float* wp = s_w + (size_t)(cch0 + cl) * 9 * COUT;
#pragma unroll
            for (int ky = 0; ky < 3; ky++)
#pragma unroll
                for (int kx = 0; kx < 3; kx++) {
                    const ull* w2 = (const ull*)(wp + (ky * 3 + kx) * COUT);
#pragma unroll
                    for (int j = 0; j < COUT / 2; j++) {
                        ull w = w2[j];
#pragma unroll
                        for (int r = 0; r < ROWS; r++)
                            fma2(acc[r][j], pv[ky + r][kx], w);
                    }
                }
        }
    }

    float* outb = out + (size_t)b * COUT * NPIX;
#pragma unroll
    for (int r = 0; r < ROWS; r++) {
        const int y = y0 + ty * ROWS + r;
#pragma unroll
        for (int j = 0; j < COUT / 2; j++) {
            float a, bb;
            unpack2(acc[r][j], a, bb);
            outb[(size_t)(2 * j)     * NPIX + y * 256 + x0 + tx] = a;
            outb[(size_t)(2 * j + 1) * NPIX + y * 256 + x0 + tx] = bb;
        }
    }
}

__global__ void __launch_bounds__(128) k_conv1(const float* __restrict__ x,
                                               const float* __restrict__ w,
                                               int b_off) {
    conv_body<9, 10, 9, 4, true>(x, w, g_p1, blockIdx.z + b_off);
}
__global__ void __launch_bounds__(128) k_conv2(const float* __restrict__ w) {
    conv_body<10, 20, 10, 4, true>(g_p1, w, g_p2, blockIdx.z);
}

// ---------------------------------------------------------------------------
// conv3 FUSED, TWO-PHASE (occupancy fix):
//  - all 20 input channels resident in smem (one load, no chunk loop)
//  - phase 0: output channels 0..26  (kappa/m epilogue, plane stores)
//  - phase 1: output channels 27..53 (H epilogue, plane + staged flat stores)
//  - accumulators: 14 pairs x 2 rows = 56 regs  ->  4 blocks/SM (16 warps)
// Shared buffer layout (floats):
//   [0, 6800)        s_in  : 20 ch x 10 rows x 34 cols
//   [6800, 11840)    s_w   : 20 ch x 9 taps x 28 out-ch (padded, 16B stride)
//   epilogue-2 overlays [0, 6912) x3 for H staging after mainloops finish.
// ---------------------------------------------------------------------------
__global__ void __launch_bounds__(128, 4) k_conv3f(const float* __restrict__ wt,
                                                   float* __restrict__ out_kap,
                                                   float* __restrict__ out_m,
                                                   float* __restrict__ out_H) {
    constexpr int CIN = 20, CP = 28;          // padded out-channels per phase
    __shared__ __align__(16) float buf[11840];  // 47360 B
    float* s_in = buf;                         // [ci][rr][cc] : ci*340+rr*34+cc
    float* s_w  = buf + 6800;                  // [(ci*9+tap)*28 + co]

    const int b  = blockIdx.z;
    const int x0 = blockIdx.x * 32;
    const int y0 = blockIdx.y * 8;
    const int tx = threadIdx.x;
    const int ty = threadIdx.y;
    const int tid = ty * 32 + tx;

    const float* inb = g_p2 + (size_t)b * CIN * NPIX;

    // load all input channels (halo 10x34)
    for (int i = tid; i < CIN * 340; i += 128) {
        int ci = i / 340;
        int rr = (i / 34) % 10;
        int cc = i % 34;
        int gy = y0 + rr - 1, gx = x0 + cc - 1;
        float v = 0.0f;
        if ((unsigned)gy < 256u && (unsigned)gx < 256u)
            v = inb[(size_t)ci * NPIX + gy * 256 + gx];
        s_in[i] = v;
    }
    // load phase-0 weights (channels 0..26, pad 27)
    for (int i = tid; i < CIN * 9 * CP; i += 128) {
        int co = i % CP;
        int r  = i / CP;
        int ci = r / 9, tap = r % 9;
        s_w[i] = (co < 27) ? wt[(co * CIN + ci) * 9 + tap] : 0.0f;
    }
    __syncthreads();

    const size_t pb   = (size_t)b * NT * NPIX;
    const size_t pix0 = (size_t)(y0 + ty * 2) * 256 + (x0 + tx);
    float* okb = out_kap + (size_t)b * 9 * NPIX;
    float* omb = out_m   + (size_t)b * 18 * NPIX;

    // ---------------- phase 0 mainloop ----------------
    ull acc[2][14];
#pragma unroll
    for (int r = 0; r < 2; r++)
#pragma unroll
        for (int j = 0; j < 14; j++) acc[r][j] = 0ull;

#pragma unroll 1
    for (int ci = 0; ci < CIN; ++ci) {
        ull pv[4][3];
#pragma unroll
        for (int rr = 0; rr < 4; rr++)
#pragma unroll
            for (int c = 0; c < 3; c++) {
                float vv = s_in[ci * 340 + (ty * 2 + rr) * 34 + tx + c];
                pv[rr][c] = pack2(vv, vv);
            }
        const float* wp = s_w + ci * 9 * CP;
#pragma unroll
        for (int ky = 0; ky < 3; ky++)
#pragma unroll
            for (int kx = 0; kx < 3; kx++) {
                const ulonglong2* w4 = (const ulonglong2*)(wp + (ky * 3 + kx) * CP);
#pragma unroll
                for (int j2 = 0; j2 < 7; j2++) {
                    ulonglong2 ww = w4[j2];
#pragma unroll
                    for (int r = 0; r < 2; r++) {
                        fma2(acc[r][2 * j2],     pv[ky + r][kx], ww.x);
                        fma2(acc[r][2 * j2 + 1], pv[ky + r][kx], ww.y);
                    }
                }
            }
    }

    __syncthreads();                 // done reading phase-0 weights
    // reload weights for phase 1 (channels 27..53, pad)
    for (int i = tid; i < CIN * 9 * CP; i += 128) {
        int co = i % CP;
        int r  = i / CP;
        int ci = r / 9, tap = r % 9;
        s_w[i] = (co < 27) ? wt[((27 + co) * CIN + ci) * 9 + tap] : 0.0f;
    }

    // phase-0 epilogue: kappa (ch 0..8, sp10) + m (ch 9..26), plane layout
#pragma unroll
    for (int r = 0; r < 2; r++) {
        const size_t pix = pix0 + (size_t)r * 256;
#pragma unroll
        for (int j = 0; j < 13; j++) {
            float lo, hi;
            unpack2(acc[r][j], lo, hi);
            const int c0 = 2 * j, c1 = 2 * j + 1;
            if (c0 < 9) okb[(size_t)c0 * NPIX + pix] = sp10(lo);
            else        omb[(size_t)(c0 - 9) * NPIX + pix] = lo;
            if (c1 < 9) okb[(size_t)c1 * NPIX + pix] = sp10(hi);
            else        omb[(size_t)(c1 - 9) * NPIX + pix] = hi;
        }
        {
            float lo, hi;
            unpack2(acc[r][13], lo, hi);
            omb[(size_t)17 * NPIX + pix] = lo;   // ch 26; hi is pad
        }
    }
    __syncthreads();                 // phase-1 weights visible

    // ---------------- phase 1 mainloop ----------------
#pragma unroll
    for (int r = 0; r < 2; r++)
#pragma unroll
        for (int j = 0; j < 14; j++) acc[r][j] = 0ull;

#pragma unroll 1
    for (int ci = 0; ci < CIN; ++ci) {
        ull pv[4][3];
#pragma unroll
        for (int rr = 0; rr < 4; rr++)
#pragma unroll
            for (int c = 0; c < 3; c++) {
                float vv = s_in[ci * 340 + (ty * 2 + rr) * 34 + tx + c];
                pv[rr][c] = pack2(vv, vv);
            }
        const float* wp = s_w + ci * 9 * CP;
#pragma unroll
        for (int ky = 0; ky < 3; ky++)
#pragma unroll
            for (int kx = 0; kx < 3; kx++) {
                const ulonglong2* w4 = (const ulonglong2*)(wp + (ky * 3 + kx) * CP);
#pragma unroll
                for (int j2 = 0; j2 < 7; j2++) {
                    ulonglong2 ww = w4[j2];
#pragma unroll
                    for (int r = 0; r < 2; r++) {
                        fma2(acc[r][2 * j2],     pv[ky + r][kx], ww.x);
                        fma2(acc[r][2 * j2 + 1], pv[ky + r][kx], ww.y);
                    }
                }
            }
    }
    __syncthreads();                 // all reads of s_in/s_w complete

    // phase-1 epilogue: H planes + staged flat stores (overlay buf)
    float* sf = buf;                 // 3 x 2304 floats = 27648 B <= 47360
#pragma unroll
    for (int r = 0; r < 2; r++) {
        float vh[27];                // co 0..26 -> real ch 27+co
#pragma unroll
        for (int j = 0; j < 13; j++)
            unpack2(acc[r][j], vh[2 * j], vh[2 * j + 1]);
        {
            float lo, hi;
            unpack2(acc[r][13], lo, hi);
            vh[26] = lo;             // hi is pad
        }
        const size_t pix = pix0 + (size_t)r * 256;
        float* st = sf + (size_t)(ty * 2 + r) * 288 + tx * 9;
#pragma unroll
        for (int t = 0; t < 9; t++) {
            float gsp = sp10(vh[t]);
            float vx  = vh[9 + t];
            float vy  = vh[18 + t];
            float h00 = gsp + vx * vx;
            float cd  = vx * vy;
            float h11 = gsp + vy * vy;
            g_H11[pb + (size_t)t * NPIX + pix] = h00;
            g_HB [pb + (size_t)t * NPIX + pix] = 2.0f * cd;
            g_H22[pb + (size_t)t * NPIX + pix] = h11;
            st[t]            = h00;
            st[2304 + t]     = cd;
            st[2 * 2304 + t] = h11;
        }
    }
    __syncthreads();
    {
        float4* d00 = (float4*)(out_H + (size_t)(b * 4 + 0) * 9 * NPIX);
        float4* d01 = (float4*)(out_H + (size_t)(b * 4 + 1) * 9 * NPIX);
        float4* d10 = (float4*)(out_H + (size_t)(b * 4 + 2) * 9 * NPIX);
        float4* d11 = (float4*)(out_H + (size_t)(b * 4 + 3) * 9 * NPIX);
        const int xo4 = x0 * 9 / 4;
        for (int i = tid; i < 576; i += 128) {
            int row = i / 72, jj = i - row * 72;
            size_t o4 = (size_t)(y0 + row) * 576 + xo4 + jj;
            int s4 = row * 72 + jj;
            float4 cd4 = ((float4*)(sf + 2304))[s4];
            d00[o4] = ((float4*)sf)[s4];
            d01[o4] = cd4;
            d10[o4] = cd4;
            d11[o4] = ((float4*)(sf + 2 * 2304))[s4];
        }
    }
}

// ---------------------------------------------------------------------------
// KG/M1/M2 grids from the flat outputs (scrambled reinterpretation):
//   g_KG[b,t,n] = out_kap_flat[b, n*9+t]
// ---------------------------------------------------------------------------
__global__ void __launch_bounds__(256) k_gridkgm(const float* __restrict__ ok,
                                                 const float* __restrict__ om) {
    __shared__ float sk[2304], s1[2304], s2[2304];
    const int blk = blockIdx.x;
    const int b  = blk >> 8;
    const int n0 = (blk & 255) * 256;
    const int tid = threadIdx.x;

    const float4* pk  = (const float4*)(ok + (size_t)b * 9 * NPIX + (size_t)n0 * 9);
    const float4* pm1 = (const float4*)(om + (size_t)b * 18 * NPIX + (size_t)n0 * 9);
    const float4* pm2 = (const float4*)(om + (size_t)b * 18 * NPIX + (size_t)9 * NPIX + (size_t)n0 * 9);
    for (int i = tid; i < 576; i += 256) {
        ((float4*)sk)[i] = pk[i];
        ((float4*)s1)[i] = pm1[i];
        ((float4*)s2)[i] = pm2[i];
    }
    __syncthreads();

    const int n = n0 + tid;
    const size_t gb = (size_t)b * NT * NPIX + n;
#pragma unroll
    for (int t = 0; t < 9; t++) {
        g_KG[gb + (size_t)t * NPIX] = sk[tid * 9 + t];
        g_M1[gb + (size_t)t * NPIX] = s1[tid * 9 + t];
        g_M2[gb + (size_t)t * NPIX] = s2[tid * 9 + t];
    }
}

// ---------------------------------------------------------------------------
// Fused stencil (unchanged): w = M(xg) on 34x34 halo, v = M(w) on 32x32,
// accumulate x_out terms with rotating registers.
// ---------------------------------------------------------------------------
__device__ __forceinline__ float stencil_A(float u, float xpv, float xmv,
                                           float ypv, float ymv,
                                           float pp, float pm, float mp, float mm,
                                           float kap, float m1, float m2,
                                           float h11, float hb, float h22) {
    return kap * kap * u
         + m1 * 0.5f * (xpv - xmv)
         + m2 * 0.5f * (ypv - ymv)
         - (h11 * (xpv - 2.0f * u + xmv)
            + hb * 0.25f * ((pp - pm) - (mp - mm))
            + h22 * (ypv - 2.0f * u + ymv));
}

__global__ void __launch_bounds__(256) k_stencil(const float* __restrict__ x) {
    __shared__ float s_xg[36][37];
    __shared__ float s_co[6][34][35];
    __shared__ float s_w[34][36];
    __shared__ float s_red[8];

    const int b  = blockIdx.z;
    const int a0 = blockIdx.y * 32;
    const int c0 = blockIdx.x * 32;
    const int tid = threadIdx.x;

    float xgp[4], wprev[4];
#pragma unroll
    for (int j = 0; j < 4; j++) { xgp[j] = 0.0f; wprev[j] = 0.0f; }
    float acc = 0.0f;

    for (int t = 0; t < 9; t++) {
        __syncthreads();
        const float* xp = x + (size_t)(b * 9 + t) * NPIX;
        for (int i = tid; i < 1296; i += 256) {
            int xr = i / 36, xc = i - xr * 36;
            int gc = c0 - 2 + xr, ga = a0 - 2 + xc;
            float v = 0.0f;
            if ((unsigned)gc < 256u && (unsigned)ga < 256u)
                v = xp[gc * 256 + ga];
            s_xg[xc][xr] = v;
        }
        const size_t pbase = (size_t)(b * 9 + t) * NPIX;
        for (int i = tid; i < 1156; i += 256) {
            int r = i / 34, c = i - r * 34;
            int ga = a0 - 1 + r, gc = c0 - 1 + c;
            bool ok = ((unsigned)ga < 256u) && ((unsigned)gc < 256u);
            size_t idx = pbase + (size_t)ga * 256 + gc;
            s_co[0][r][c] = ok ? g_KG [idx] : 0.0f;
            s_co[1][r][c] = ok ? g_M1 [idx] : 0.0f;
            s_co[2][r][c] = ok ? g_M2 [idx] : 0.0f;
            s_co[3][r][c] = ok ? g_H11[idx] : 0.0f;
            s_co[4][r][c] = ok ? g_HB [idx] : 0.0f;
            s_co[5][r][c] = ok ? g_H22[idx] : 0.0f;
        }
        __syncthreads();

        for (int i = tid; i < 1156; i += 256) {
            int r = i / 34, c = i - r * 34;
            int ga = a0 - 1 + r, gc = c0 - 1 + c;
            float w = 0.0f;
            if ((unsigned)ga < 256u && (unsigned)gc < 256u) {
                float u   = s_xg[r + 1][c + 1];
                float xpv = s_xg[r + 2][c + 1], xmv = s_xg[r][c + 1];
                float ypv = s_xg[r + 1][c + 2], ymv = s_xg[r + 1][c];
                float pp  = s_xg[r + 2][c + 2], pm  = s_xg[r + 2][c];
                float mp  = s_xg[r][c + 2],     mm  = s_xg[r][c];
                w = u + stencil_A(u, xpv, xmv, ypv, ymv, pp, pm, mp, mm,
                                  s_co[0][r][c], s_co[1][r][c], s_co[2][r][c],
                                  s_co[3][r][c], s_co[4][r][c], s_co[5][r][c]);
            }
            s_w[r][c] = w;
        }
        __syncthreads();

#pragma unroll
        for (int j = 0; j < 4; j++) {
            int p = tid + j * 256;
            int r = p >> 5, c = p & 31;
            float u   = s_w[r + 1][c + 1];
            float xpv = s_w[r + 2][c + 1], xmv = s_w[r][c + 1];
            float ypv = s_w[r + 1][c + 2], ymv = s_w[r + 1][c];
            float pp  = s_w[r + 2][c + 2], pm  = s_w[r + 2][c];
            float mp  = s_w[r][c + 2],     mm  = s_w[r][c];
            float v = u + stencil_A(u, xpv, xmv, ypv, ymv, pp, pm, mp, mm,
                                    s_co[0][r + 1][c + 1], s_co[1][r + 1][c + 1],
                                    s_co[2][r + 1][c + 1], s_co[3][r + 1][c + 1],
                                    s_co[4][r + 1][c + 1], s_co[5][r + 1][c + 1]);
            float xgc = s_xg[r + 2][c + 2];
            acc += xgc * v;
            if (t >= 1 && t <= 7) acc += xgc * xgc;
            if (t >= 1) acc -= u * xgp[j] + wprev[j] * xgc;
            xgp[j]   = xgc;
            wprev[j] = u;
        }
    }

#pragma unroll
    for (int o = 16; o > 0; o >>= 1)
        acc += __shfl_down_sync(0xffffffffu, acc, o);
    if ((tid & 31) == 0) s_red[tid >> 5] = acc;
    __syncthreads();
    if (tid == 0) {
        float s = 0.0f;
#pragma unroll
        for (int i = 0; i < 8; i++) s += s_red[i];
        g_part[b * 64 + blockIdx.y * 8 + blockIdx.x] = s;
    }
}

__global__ void __launch_bounds__(64) k_final(float* __restrict__ out_x) {
    __shared__ float s[2];
    int b = blockIdx.x, tid = threadIdx.x;
    float v = g_part[b * 64 + tid];
#pragma unroll
    for (int o = 16; o > 0; o >>= 1)
        v += __shfl_down_sync(0xffffffffu, v, o);
    if ((tid & 31) == 0) s[tid >> 5] = v;
    __syncthreads();
    if (tid == 0) out_x[b] = s[0] + s[1];
}

// ---------------------------------------------------------------------------
// Launch. conv1 split keeps conv3f at profiled launch slot #4.
// Output: [x_out(16)] [kappa_r 16*9*65536] [m_r 16*18*65536] [H_r 16*4*9*65536]
// ---------------------------------------------------------------------------
extern "C" void kernel_launch(void* const* d_in, const int* in_sizes, int n_in,
                              void* d_out, int out_size) {
    (void)in_sizes; (void)n_in; (void)out_size;
    const float* x  = (const float*)d_in[0];
    const float* w1 = (const float*)d_in[4];
    const float* w2 = (const float*)d_in[5];
    const float* w3 = (const float*)d_in[6];

    float* out     = (float*)d_out;
    float* out_kap = out + 16;
    float* out_m   = out + 16 + (size_t)NB * 9 * NPIX;
    float* out_H   = out + 16 + (size_t)NB * 9 * NPIX + (size_t)NB * 18 * NPIX;

    dim3 cb(32, 4);
    k_conv1 <<<dim3(8, 16, 8),  cb>>>(x, w1, 0);
    k_conv1 <<<dim3(8, 16, 8),  cb>>>(x, w1, 8);
    k_conv2 <<<dim3(8, 16, NB), cb>>>(w2);
    k_conv3f<<<dim3(8, 32, NB), cb>>>(w3, out_kap, out_m, out_H);

    k_gridkgm<<<4096, 256>>>(out_kap, out_m);

    k_stencil<<<dim3(8, 8, NB), 256>>>(x);
    k_final  <<<NB, 64>>>(out);
}